// round 1
// baseline (speedup 1.0000x reference)
#include <cuda_runtime.h>
#include <math.h>

#define B_MAX 2048
#define LMAX 100
#define DDIM 256
#define POS_DIM 50
#define ROWBLK 25   // 100 % 25 == 0 -> no out-of-bounds smem rows

__device__ int g_offs[B_MAX];

// ---------------- exclusive prefix sum of doc_lens ----------------
__global__ void scan_kernel(const int* __restrict__ dl, int B) {
    __shared__ int sh[B_MAX];
    __shared__ int wsum[8];
    int t = threadIdx.x; // 256 threads
    for (int i = t; i < B_MAX; i += 256) sh[i] = (i < B) ? dl[i] : 0;
    __syncthreads();
    int base = t * 8;
    int ex[8]; int run = 0;
#pragma unroll
    for (int k = 0; k < 8; k++) { ex[k] = run; run += sh[base + k]; }
    int lane = t & 31, w = t >> 5;
    int inc = run;
#pragma unroll
    for (int st = 1; st < 32; st <<= 1) {
        int x = __shfl_up_sync(0xffffffffu, inc, st);
        if (lane >= st) inc += x;
    }
    if (lane == 31) wsum[w] = inc;
    __syncthreads();
    int wbase = 0;
    for (int i = 0; i < w; i++) wbase += wsum[i];
    int chunk_ex = wbase + inc - run;
#pragma unroll
    for (int k = 0; k < 8; k++)
        if (base + k < B) g_offs[base + k] = chunk_ex + ex[k];
}

__device__ __forceinline__ float warp_reduce(float v) {
#pragma unroll
    for (int st = 16; st; st >>= 1) v += __shfl_xor_sync(0xffffffffu, v, st);
    return v;
}

// ---------------- fused per-document kernel (1 CTA per doc) ----------------
__global__ void __launch_bounds__(256) summa_kernel(
    const float* __restrict__ sent,       // [B,L,D]
    const float* __restrict__ fc_w,       // [D,D]
    const float* __restrict__ fc_b,       // [D]
    const float* __restrict__ w_content,  // [D]
    const float* __restrict__ W_sal,      // [D,D]
    const float* __restrict__ W_nov,      // [D,D]
    const float* __restrict__ abs_embed,  // [100,50]
    const float* __restrict__ rel_embed,  // [25,50]
    const float* __restrict__ w_abs,      // [50]
    const float* __restrict__ w_rel,      // [50]
    const float* __restrict__ bias,       // [1]
    const int*   __restrict__ doc_lens,   // [B]
    float* __restrict__ out)
{
    extern __shared__ float S[];          // [LMAX][DDIM], 100 KB; becomes G in-place
    __shared__ float docsv[DDIM];
    __shared__ float docv[DDIM];
    __shared__ float u[DDIM];
    __shared__ float pre[LMAX];
    __shared__ float wred[2][8];

    const int b    = blockIdx.x;
    const int tid  = threadIdx.x;
    const int lane = tid & 31;
    const int w    = tid >> 5;
    const int dl   = doc_lens[b];
    const float dlf = (float)dl;
    const float* sb = sent + (size_t)b * LMAX * DDIM;

    // ---- Phase 1: load valid sent rows into smem (coalesced float4) ----
    {
        const float4* src = (const float4*)sb;
        float4* dst = (float4*)S;
        const int n4 = dl * (DDIM / 4);
        for (int i = tid; i < n4; i += 256) dst[i] = src[i];
    }
    __syncthreads();

    // ---- Phase 2: docs = mean over valid rows (thread e owns column e) ----
    {
        float a = 0.f;
        for (int t = 0; t < dl; t++) a += S[t * DDIM + tid];
        docsv[tid] = __fdiv_rn(a, dlf);
    }
    __syncthreads();

    // ---- Phase 3: doc = tanh(fc_w @ docs + fc_b)   (row-per-warp matvec) ----
    for (int r = 0; r < 32; r++) {
        int d = w * 32 + r;
        float a = 0.f;
#pragma unroll
        for (int k = 0; k < 8; k++)
            a += fc_w[d * DDIM + lane + 32 * k] * docsv[lane + 32 * k];
        a = warp_reduce(a);
        if (lane == 0) docv[d] = tanhf(a + fc_b[d]);
    }
    __syncthreads();

    // ---- Phase 4: u = w_content + W_sal @ doc ----
    for (int r = 0; r < 32; r++) {
        int d = w * 32 + r;
        float a = 0.f;
#pragma unroll
        for (int k = 0; k < 8; k++)
            a += W_sal[d * DDIM + lane + 32 * k] * docv[lane + 32 * k];
        a = warp_reduce(a);
        if (lane == 0) u[d] = a + w_content[d];
    }
    __syncthreads();

    // ---- Phase 5: pre[t] = sent[t]·u + abs + rel + bias  (warp per row) ----
    {
        const float b0 = bias[0];
        for (int t = w; t < dl; t += 8) {
            float a = 0.f;
#pragma unroll
            for (int k = 0; k < 8; k++)
                a += S[t * DDIM + lane + 32 * k] * u[lane + 32 * k];
            // ties-to-even on an IEEE-rounded division (matches jnp.round)
            int ri = (int)rintf(__fdiv_rn((float)(t + 1) * 9.0f, dlf));
            if (lane < POS_DIM)
                a += abs_embed[t * POS_DIM + lane] * w_abs[lane]
                   + rel_embed[ri * POS_DIM + lane] * w_rel[lane];
            if (lane + 32 < POS_DIM)
                a += abs_embed[t * POS_DIM + lane + 32] * w_abs[lane + 32]
                   + rel_embed[ri * POS_DIM + lane + 32] * w_rel[lane + 32];
            a = warp_reduce(a);
            if (lane == 0) pre[t] = a + b0;
        }
    }
    __syncthreads();

    // ---- Phase 6: in-place GEMM  S <- S @ W_nov   ([dl,256]x[256,256]) ----
    // thread j owns output column j; ROWBLK rows accumulated in registers.
    {
        const int j = tid;
        for (int t0 = 0; t0 < dl; t0 += ROWBLK) {
            float acc[ROWBLK];
#pragma unroll
            for (int r = 0; r < ROWBLK; r++) acc[r] = 0.f;
            for (int d = 0; d < DDIM; d += 4) {
                float w0 = W_nov[(d + 0) * DDIM + j];
                float w1 = W_nov[(d + 1) * DDIM + j];
                float w2 = W_nov[(d + 2) * DDIM + j];
                float w3 = W_nov[(d + 3) * DDIM + j];
#pragma unroll
                for (int r = 0; r < ROWBLK; r++) {
                    float4 sv = *(const float4*)&S[(t0 + r) * DDIM + d]; // broadcast
                    acc[r] += sv.x * w0;
                    acc[r] += sv.y * w1;
                    acc[r] += sv.z * w2;
                    acc[r] += sv.w * w3;
                }
            }
            __syncthreads();  // all reads of this row-block done before overwrite
#pragma unroll
            for (int r = 0; r < ROWBLK; r++)
                if (t0 + r < dl) S[(t0 + r) * DDIM + j] = acc[r];
            __syncthreads();
        }
    }

    // ---- Phase 7: recurrence  p_t = sigmoid(pre_t - g_t·tanh(s_t)); s += p h ----
    {
        const int e = tid;
        const int off = g_offs[b];
        float s_e = 0.f;
        float h_e = sb[e];  // row 0 prefetched (re-read from L2-hot global)
        for (int t = 0; t < dl; t++) {
            float ts = tanhf(s_e);
            float part = S[t * DDIM + e] * ts;
            part = warp_reduce(part);
            if (lane == 0) wred[t & 1][w] = part;
            float h_next = (t + 1 < dl) ? sb[(t + 1) * DDIM + e] : 0.f; // prefetch
            __syncthreads();
            float dot = 0.f;
#pragma unroll
            for (int k = 0; k < 8; k++) dot += wred[t & 1][k];
            float p = __fdiv_rn(1.f, 1.f + expf(dot - pre[t]));
            s_e = fmaf(p, h_e, s_e);
            h_e = h_next;
            if (tid == 0) out[off + t] = p;
        }
    }
}

// ---------------- launch ----------------
extern "C" void kernel_launch(void* const* d_in, const int* in_sizes, int n_in,
                              void* d_out, int out_size) {
    const float* sent      = (const float*)d_in[0];
    const float* fc_w      = (const float*)d_in[1];
    const float* fc_b      = (const float*)d_in[2];
    const float* w_content = (const float*)d_in[3];
    const float* W_sal     = (const float*)d_in[4];
    const float* W_nov     = (const float*)d_in[5];
    const float* abs_e     = (const float*)d_in[6];
    const float* rel_e     = (const float*)d_in[7];
    const float* w_abs     = (const float*)d_in[8];
    const float* w_rel     = (const float*)d_in[9];
    const float* bias      = (const float*)d_in[10];
    const int*   doc_lens  = (const int*)d_in[11];
    const int B = in_sizes[11];

    const int smem = LMAX * DDIM * sizeof(float); // 102400 B
    cudaFuncSetAttribute(summa_kernel,
                         cudaFuncAttributeMaxDynamicSharedMemorySize, smem);

    scan_kernel<<<1, 256>>>(doc_lens, B);
    summa_kernel<<<B, 256, smem>>>(sent, fc_w, fc_b, w_content, W_sal, W_nov,
                                   abs_e, rel_e, w_abs, w_rel, bias, doc_lens,
                                   (float*)d_out);
}

// round 3
// speedup vs baseline: 1.9302x; 1.9302x over previous
#include <cuda_runtime.h>
#include <cuda_bf16.h>
#include <math.h>
#include <cstdint>

#define B_MAX 2048
#define LMAX 100
#define DDIM 256
#define POS_DIM 50

__device__ int g_offs[B_MAX];
// G = sent_flat @ W_nov (fp32)
__device__ float g_G[(size_t)B_MAX * LMAX * DDIM];
// W_nov transposed + split into bf16 hi/lo: Wt[n][k] = W_nov[k][n]
__device__ __nv_bfloat16 g_Wt_hi[DDIM * DDIM];
__device__ __nv_bfloat16 g_Wt_lo[DDIM * DDIM];

__device__ __forceinline__ uint32_t smem_u32(const void* p) {
    uint32_t a;
    asm("{ .reg .u64 t; cvta.to.shared.u64 t, %1; cvt.u32.u64 %0, t; }"
        : "=r"(a) : "l"(p));
    return a;
}

#define LDSM4(r, addr) \
    asm volatile("ldmatrix.sync.aligned.m8n8.x4.shared.b16 {%0,%1,%2,%3}, [%4];" \
        : "=r"((r)[0]), "=r"((r)[1]), "=r"((r)[2]), "=r"((r)[3]) : "r"(addr))

#define MMA_BF16(c, a, b0, b1) \
    asm volatile("mma.sync.aligned.m16n8k16.row.col.f32.bf16.bf16.f32 " \
        "{%0,%1,%2,%3},{%4,%5,%6,%7},{%8,%9},{%0,%1,%2,%3};" \
        : "+f"((c)[0]), "+f"((c)[1]), "+f"((c)[2]), "+f"((c)[3]) \
        : "r"((a)[0]), "r"((a)[1]), "r"((a)[2]), "r"((a)[3]), "r"(b0), "r"(b1))

// ======================= prefix sum of doc_lens =======================
__global__ void scan_kernel(const int* __restrict__ dl, int B) {
    __shared__ int sh[B_MAX];
    __shared__ int wsum[8];
    int t = threadIdx.x;
    for (int i = t; i < B_MAX; i += 256) sh[i] = (i < B) ? dl[i] : 0;
    __syncthreads();
    int base = t * 8;
    int ex[8]; int run = 0;
#pragma unroll
    for (int k = 0; k < 8; k++) { ex[k] = run; run += sh[base + k]; }
    int lane = t & 31, w = t >> 5;
    int inc = run;
#pragma unroll
    for (int st = 1; st < 32; st <<= 1) {
        int x = __shfl_up_sync(0xffffffffu, inc, st);
        if (lane >= st) inc += x;
    }
    if (lane == 31) wsum[w] = inc;
    __syncthreads();
    int wbase = 0;
    for (int i = 0; i < w; i++) wbase += wsum[i];
    int chunk_ex = wbase + inc - run;
#pragma unroll
    for (int k = 0; k < 8; k++)
        if (base + k < B) g_offs[base + k] = chunk_ex + ex[k];
}

// ======================= W_nov transpose + bf16 hi/lo split =======================
__global__ void prep_kernel(const float* __restrict__ Wn) {
    int idx = blockIdx.x * 256 + threadIdx.x;      // 65536 total
    int n = idx >> 8, k = idx & 255;
    float w = Wn[k * DDIM + n];
    __nv_bfloat16 h = __float2bfloat16_rn(w);
    g_Wt_hi[n * DDIM + k] = h;
    g_Wt_lo[n * DDIM + k] = __float2bfloat16_rn(w - __bfloat162float(h));
}

// ======================= HMMA GEMM: G = sent_flat @ W_nov =======================
// CTA tile 128(M) x 128(N), K=256 in 4 chunks of 64.
// 3-pass bf16 split: hi*Whi + hi*Wlo + lo*Whi, fp32 accumulators.
// smem rows padded to 72 bf16 (144 B) -> conflict-free ldmatrix.
#define AS_HI 0
#define AS_LO 18432
#define BS_HI 36864
#define BS_LO 55296
#define GSM_TOTAL 73728

__global__ void __launch_bounds__(256, 2) gemm_kernel(const float* __restrict__ sent,
                                                      int rows)
{
    extern __shared__ char sm[];
    const uint32_t sb = smem_u32(sm);
    const int tid = threadIdx.x, lane = tid & 31, wid = tid >> 5;
    const int wm = wid & 1, wn = wid >> 1;           // warp grid 2(M) x 4(N)
    const int gm0 = blockIdx.x * 128;
    const int n0  = blockIdx.y * 128;

    // ldmatrix per-lane source coordinates
    const int alr = lane & 15;                       // A: row in 16
    const int alc = (lane & 16) >> 1;                // A: col offset 0/8
    const int blr = (lane & 7) | ((lane >> 1) & 8);  // B: row in 16
    const int blc = lane & 8;                        // B: col offset 0/8

    const uint32_t a_base = sb + AS_HI + (uint32_t)(((wm * 64 + alr) * 72 + alc) * 2);
    const uint32_t b_base = sb + BS_HI + (uint32_t)(((wn * 32 + blr) * 72 + blc) * 2);

    float c[4][4][4];
#pragma unroll
    for (int mt = 0; mt < 4; mt++)
#pragma unroll
        for (int nf = 0; nf < 4; nf++)
#pragma unroll
            for (int r = 0; r < 4; r++) c[mt][nf][r] = 0.f;

    for (int ch = 0; ch < 4; ch++) {
        const int k0 = ch * 64;
        // ---- stage A chunk (128 x 64 fp32 -> bf16 hi/lo) ----
#pragma unroll
        for (int i = 0; i < 8; i++) {
            int idx = tid + i * 256;                 // 2048
            int m = idx >> 4, kq = idx & 15;
            float4 v = make_float4(0.f, 0.f, 0.f, 0.f);
            if (gm0 + m < rows)
                v = *(const float4*)&sent[(size_t)(gm0 + m) * DDIM + k0 + kq * 4];
            __nv_bfloat162 h0, h1, l0, l1;
            h0.x = __float2bfloat16_rn(v.x); h0.y = __float2bfloat16_rn(v.y);
            h1.x = __float2bfloat16_rn(v.z); h1.y = __float2bfloat16_rn(v.w);
            l0.x = __float2bfloat16_rn(v.x - __bfloat162float(h0.x));
            l0.y = __float2bfloat16_rn(v.y - __bfloat162float(h0.y));
            l1.x = __float2bfloat16_rn(v.z - __bfloat162float(h1.x));
            l1.y = __float2bfloat16_rn(v.w - __bfloat162float(h1.y));
            uint2 hp = make_uint2(*(uint32_t*)&h0, *(uint32_t*)&h1);
            uint2 lp = make_uint2(*(uint32_t*)&l0, *(uint32_t*)&l1);
            *(uint2*)(sm + AS_HI + m * 144 + kq * 8) = hp;
            *(uint2*)(sm + AS_LO + m * 144 + kq * 8) = lp;
        }
        // ---- stage B chunk (128 x 64 bf16, already transposed in global) ----
#pragma unroll
        for (int i = 0; i < 4; i++) {
            int idx = tid + i * 256;                 // 1024
            int n = idx >> 3, k4 = idx & 7;
            *(float4*)(sm + BS_HI + n * 144 + k4 * 16) =
                *(const float4*)&g_Wt_hi[(size_t)(n0 + n) * DDIM + k0 + k4 * 8];
            *(float4*)(sm + BS_LO + n * 144 + k4 * 16) =
                *(const float4*)&g_Wt_lo[(size_t)(n0 + n) * DDIM + k0 + k4 * 8];
        }
        __syncthreads();

#pragma unroll
        for (int ks = 0; ks < 4; ks++) {
            uint32_t ah[4][4], al[4][4], bh[2][4], bl[2][4];
#pragma unroll
            for (int mt = 0; mt < 4; mt++)
                LDSM4(ah[mt], a_base + mt * 2304 + ks * 32);
#pragma unroll
            for (int nt = 0; nt < 2; nt++) {
                LDSM4(bh[nt], b_base + nt * 2304 + ks * 32);
                LDSM4(bl[nt], b_base + 18432u + nt * 2304 + ks * 32);
            }
            // pass 1: hi * Whi ; pass 2: hi * Wlo
#pragma unroll
            for (int mt = 0; mt < 4; mt++)
#pragma unroll
                for (int nf = 0; nf < 4; nf++) {
                    MMA_BF16(c[mt][nf], ah[mt], bh[nf >> 1][(nf & 1) * 2],
                             bh[nf >> 1][(nf & 1) * 2 + 1]);
                    MMA_BF16(c[mt][nf], ah[mt], bl[nf >> 1][(nf & 1) * 2],
                             bl[nf >> 1][(nf & 1) * 2 + 1]);
                }
            // pass 3: lo * Whi
#pragma unroll
            for (int mt = 0; mt < 4; mt++)
                LDSM4(al[mt], a_base + 18432u + mt * 2304 + ks * 32);
#pragma unroll
            for (int mt = 0; mt < 4; mt++)
#pragma unroll
                for (int nf = 0; nf < 4; nf++)
                    MMA_BF16(c[mt][nf], al[mt], bh[nf >> 1][(nf & 1) * 2],
                             bh[nf >> 1][(nf & 1) * 2 + 1]);
        }
        __syncthreads();   // protect smem reuse (next chunk / epilogue)
    }

    // ---- epilogue: frags -> smem stage (pitch 132) -> coalesced fp32 STG ----
    float* stage = (float*)sm;
    const int gID = lane >> 2, tg = lane & 3;
    for (int mh = 0; mh < 2; mh++) {
        if (wm == mh) {
#pragma unroll
            for (int mt = 0; mt < 4; mt++)
#pragma unroll
                for (int nf = 0; nf < 4; nf++) {
                    int r = mt * 16 + gID;
                    int cc = wn * 32 + nf * 8 + tg * 2;
                    *(float2*)&stage[r * 132 + cc] =
                        make_float2(c[mt][nf][0], c[mt][nf][1]);
                    *(float2*)&stage[(r + 8) * 132 + cc] =
                        make_float2(c[mt][nf][2], c[mt][nf][3]);
                }
        }
        __syncthreads();
#pragma unroll
        for (int i = 0; i < 8; i++) {
            int idx = tid + i * 256;                 // 2048
            int r = idx >> 5, c4 = idx & 31;
            int grow = gm0 + mh * 64 + r;
            if (grow < rows)
                *(float4*)&g_G[(size_t)grow * DDIM + n0 + c4 * 4] =
                    *(float4*)&stage[r * 132 + c4 * 4];
        }
        __syncthreads();
    }
}

__device__ __forceinline__ float warp_reduce(float v) {
#pragma unroll
    for (int st = 16; st; st >>= 1) v += __shfl_xor_sync(0xffffffffu, v, st);
    return v;
}

// ======================= fused per-document kernel =======================
__global__ void __launch_bounds__(256) summa_kernel(
    const float* __restrict__ sent, const float* __restrict__ fc_w,
    const float* __restrict__ fc_b, const float* __restrict__ w_content,
    const float* __restrict__ W_sal, const float* __restrict__ abs_embed,
    const float* __restrict__ rel_embed, const float* __restrict__ w_abs,
    const float* __restrict__ w_rel, const float* __restrict__ bias,
    const int* __restrict__ doc_lens, float* __restrict__ out)
{
    __shared__ float docsv[DDIM];
    __shared__ float docv[DDIM];
    __shared__ float u[DDIM];
    __shared__ float pre[LMAX];
    __shared__ float wred[2][8];

    const int b = blockIdx.x;
    const int tid = threadIdx.x;
    const int lane = tid & 31;
    const int w = tid >> 5;
    const int dl = doc_lens[b];
    const float dlf = (float)dl;
    const float* sbp = sent + (size_t)b * LMAX * DDIM;
    const float* gbp = g_G + (size_t)b * LMAX * DDIM;

    // docs = mean over valid rows (thread e owns column e)
    {
        float a = 0.f;
        for (int t = 0; t < dl; t++) a += sbp[t * DDIM + tid];
        docsv[tid] = __fdiv_rn(a, dlf);
    }
    __syncthreads();

    // doc = tanh(fc_w @ docs + fc_b)
    for (int r = 0; r < 32; r++) {
        int d = w * 32 + r;
        float a = 0.f;
#pragma unroll
        for (int k = 0; k < 8; k++)
            a += fc_w[d * DDIM + lane + 32 * k] * docsv[lane + 32 * k];
        a = warp_reduce(a);
        if (lane == 0) docv[d] = tanhf(a + fc_b[d]);
    }
    __syncthreads();

    // u = w_content + W_sal @ doc
    for (int r = 0; r < 32; r++) {
        int d = w * 32 + r;
        float a = 0.f;
#pragma unroll
        for (int k = 0; k < 8; k++)
            a += W_sal[d * DDIM + lane + 32 * k] * docv[lane + 32 * k];
        a = warp_reduce(a);
        if (lane == 0) u[d] = a + w_content[d];
    }
    __syncthreads();

    // pre[t] = sent[t].u + abs + rel + bias (warp per row)
    {
        const float b0 = bias[0];
        for (int t = w; t < dl; t += 8) {
            float a = 0.f;
#pragma unroll
            for (int k = 0; k < 8; k++)
                a += sbp[t * DDIM + lane + 32 * k] * u[lane + 32 * k];
            int ri = (int)rintf(__fdiv_rn((float)(t + 1) * 9.0f, dlf));
            if (lane < POS_DIM)
                a += abs_embed[t * POS_DIM + lane] * w_abs[lane]
                   + rel_embed[ri * POS_DIM + lane] * w_rel[lane];
            if (lane + 32 < POS_DIM)
                a += abs_embed[t * POS_DIM + lane + 32] * w_abs[lane + 32]
                   + rel_embed[ri * POS_DIM + lane + 32] * w_rel[lane + 32];
            a = warp_reduce(a);
            if (lane == 0) pre[t] = a + b0;
        }
    }
    __syncthreads();

    // recurrence: p_t = sigmoid(pre_t - g_t.tanh(s_t)); s += p*h
    {
        const int off = g_offs[b];
        float s_e = 0.f;
        float h_e = sbp[tid];
        float g_e = gbp[tid];
        for (int t = 0; t < dl; t++) {
            float ts = tanhf(s_e);
            float part = g_e * ts;
            part = warp_reduce(part);
            if (lane == 0) wred[t & 1][w] = part;
            float h_n = (t + 1 < dl) ? sbp[(t + 1) * DDIM + tid] : 0.f;
            float g_n = (t + 1 < dl) ? gbp[(t + 1) * DDIM + tid] : 0.f;
            __syncthreads();
            float dot = 0.f;
#pragma unroll
            for (int k = 0; k < 8; k++) dot += wred[t & 1][k];
            float p = __fdiv_rn(1.f, 1.f + expf(dot - pre[t]));
            s_e = fmaf(p, h_e, s_e);
            h_e = h_n;
            g_e = g_n;
            if (tid == 0) out[off + t] = p;
        }
    }
}

// ======================= launch =======================
extern "C" void kernel_launch(void* const* d_in, const int* in_sizes, int n_in,
                              void* d_out, int out_size) {
    const float* sent      = (const float*)d_in[0];
    const float* fc_w      = (const float*)d_in[1];
    const float* fc_b      = (const float*)d_in[2];
    const float* w_content = (const float*)d_in[3];
    const float* W_sal     = (const float*)d_in[4];
    const float* W_nov     = (const float*)d_in[5];
    const float* abs_e     = (const float*)d_in[6];
    const float* rel_e     = (const float*)d_in[7];
    const float* w_abs     = (const float*)d_in[8];
    const float* w_rel     = (const float*)d_in[9];
    const float* bias      = (const float*)d_in[10];
    const int*   doc_lens  = (const int*)d_in[11];
    const int B = in_sizes[11];
    const int rows = B * LMAX;

    cudaFuncSetAttribute(gemm_kernel,
                         cudaFuncAttributeMaxDynamicSharedMemorySize, GSM_TOTAL);

    scan_kernel<<<1, 256>>>(doc_lens, B);
    prep_kernel<<<DDIM * DDIM / 256, 256>>>(W_nov);
    dim3 ggrid((rows + 127) / 128, 2);
    gemm_kernel<<<ggrid, 256, GSM_TOTAL>>>(sent, rows);
    summa_kernel<<<B, 256>>>(sent, fc_w, fc_b, w_content, W_sal,
                             abs_e, rel_e, w_abs, w_rel, bias, doc_lens,
                             (float*)d_out);
}

// round 4
// speedup vs baseline: 2.8782x; 1.4911x over previous
#include <cuda_runtime.h>
#include <cuda_bf16.h>
#include <math.h>
#include <cstdint>

#define B_MAX 2048
#define LMAX 100
#define DDIM 256
#define POS_DIM 50

__device__ int   g_offs[B_MAX];
__device__ int   g_total_rows;
__device__ int   g_rowmap[(size_t)B_MAX * LMAX];
__device__ float g_abs_vals[LMAX];
__device__ float g_rel_vals[32];
__device__ float g_docs[(size_t)B_MAX * DDIM];
__device__ float g_doc[(size_t)B_MAX * DDIM];
__device__ float g_u[(size_t)B_MAX * DDIM];
__device__ float g_G[(size_t)B_MAX * LMAX * DDIM];           // compacted valid rows
__device__ __nv_bfloat16 g_W1h[DDIM * DDIM], g_W1l[DDIM * DDIM]; // fc_w (direct)
__device__ __nv_bfloat16 g_W2h[DDIM * DDIM], g_W2l[DDIM * DDIM]; // W_sal (direct)
__device__ __nv_bfloat16 g_W3h[DDIM * DDIM], g_W3l[DDIM * DDIM]; // W_nov (transposed)

__device__ __forceinline__ uint32_t smem_u32(const void* p) {
    uint32_t a;
    asm("{ .reg .u64 t; cvta.to.shared.u64 t, %1; cvt.u32.u64 %0, t; }"
        : "=r"(a) : "l"(p));
    return a;
}
#define LDSM4(r, addr) \
    asm volatile("ldmatrix.sync.aligned.m8n8.x4.shared.b16 {%0,%1,%2,%3}, [%4];" \
        : "=r"((r)[0]), "=r"((r)[1]), "=r"((r)[2]), "=r"((r)[3]) : "r"(addr))
#define MMA_BF16(c, a, b0, b1) \
    asm volatile("mma.sync.aligned.m16n8k16.row.col.f32.bf16.bf16.f32 " \
        "{%0,%1,%2,%3},{%4,%5,%6,%7},{%8,%9},{%0,%1,%2,%3};" \
        : "+f"((c)[0]), "+f"((c)[1]), "+f"((c)[2]), "+f"((c)[3]) \
        : "r"((a)[0]), "r"((a)[1]), "r"((a)[2]), "r"((a)[3]), "r"(b0), "r"(b1))

// ============ scan: offsets, total, position-dot precompute ============
__global__ void scan_kernel(const int* __restrict__ dl, int B,
                            const float* __restrict__ abs_e,
                            const float* __restrict__ rel_e,
                            const float* __restrict__ w_abs,
                            const float* __restrict__ w_rel) {
    __shared__ int sh[B_MAX];
    __shared__ int wsum[8];
    int t = threadIdx.x;
    for (int i = t; i < B_MAX; i += 256) sh[i] = (i < B) ? dl[i] : 0;
    __syncthreads();
    int base = t * 8;
    int ex[8]; int run = 0;
#pragma unroll
    for (int k = 0; k < 8; k++) { ex[k] = run; run += sh[base + k]; }
    int lane = t & 31, w = t >> 5;
    int inc = run;
#pragma unroll
    for (int st = 1; st < 32; st <<= 1) {
        int x = __shfl_up_sync(0xffffffffu, inc, st);
        if (lane >= st) inc += x;
    }
    if (lane == 31) wsum[w] = inc;
    __syncthreads();
    int wbase = 0;
    for (int i = 0; i < w; i++) wbase += wsum[i];
    int chunk_ex = wbase + inc - run;
#pragma unroll
    for (int k = 0; k < 8; k++)
        if (base + k < B) g_offs[base + k] = chunk_ex + ex[k];
    if (t == 0) {
        int tot = 0;
        for (int i = 0; i < 8; i++) tot += wsum[i];
        g_total_rows = tot;
    }
    // abs/rel position scalars
    if (t < LMAX) {
        float a = 0.f;
        for (int i = 0; i < POS_DIM; i++) a += abs_e[t * POS_DIM + i] * w_abs[i];
        g_abs_vals[t] = a;
    } else if (t >= 128 && t < 153) {
        int s = t - 128;
        float a = 0.f;
        for (int i = 0; i < POS_DIM; i++) a += rel_e[s * POS_DIM + i] * w_rel[i];
        g_rel_vals[s] = a;
    }
}

// ============ weight prep: bf16 hi/lo, W_nov transposed ============
__global__ void prep_kernel(const float* __restrict__ fc_w,
                            const float* __restrict__ W_sal,
                            const float* __restrict__ W_nov) {
    int idx = blockIdx.x * 256 + threadIdx.x;   // 65536
    int y = blockIdx.y;
    if (y == 0) {
        int n = idx >> 8, k = idx & 255;
        float w = W_nov[k * DDIM + n];           // transpose
        __nv_bfloat16 h = __float2bfloat16_rn(w);
        g_W3h[n * DDIM + k] = h;
        g_W3l[n * DDIM + k] = __float2bfloat16_rn(w - __bfloat162float(h));
    } else if (y == 1) {
        float w = fc_w[idx];
        __nv_bfloat16 h = __float2bfloat16_rn(w);
        g_W1h[idx] = h;
        g_W1l[idx] = __float2bfloat16_rn(w - __bfloat162float(h));
    } else {
        float w = W_sal[idx];
        __nv_bfloat16 h = __float2bfloat16_rn(w);
        g_W2h[idx] = h;
        g_W2l[idx] = __float2bfloat16_rn(w - __bfloat162float(h));
    }
}

// ============ rowmap expand (valid-prefix compaction) ============
__global__ void rowmap_kernel(const int* __restrict__ dl) {
    int b = blockIdx.x;
    int n = dl[b], off = g_offs[b];
    for (int t = threadIdx.x; t < n; t += 128)
        g_rowmap[off + t] = b * LMAX + t;
}

// ============ masked mean over valid rows ============
__global__ void __launch_bounds__(256) mean_kernel(const float* __restrict__ sent,
                                                   const int* __restrict__ dl) {
    int b = blockIdx.x, tid = threadIdx.x;
    int n = dl[b];
    const float* sbp = sent + (size_t)b * LMAX * DDIM;
    float a0 = 0.f, a1 = 0.f;
    int t = 0;
    for (; t + 1 < n; t += 2) {
        a0 += sbp[t * DDIM + tid];
        a1 += sbp[(t + 1) * DDIM + tid];
    }
    if (t < n) a0 += sbp[t * DDIM + tid];
    g_docs[b * DDIM + tid] = __fdiv_rn(a0 + a1, (float)n);
}

// ============ HMMA GEMM: C = A @ W  (3-pass bf16 split) ============
// CTA tile 128x128, K=256 in 4 chunks of 64; smem pitch 72 bf16.
// epi_mode: 0 plain store, 1 tanh(x+vec[n]), 2 x+vec[n].
#define AS_HI 0
#define AS_LO 18432
#define BS_HI 36864
#define BS_LO 55296
#define GSM_TOTAL 73728

__global__ void __launch_bounds__(256, 2) gemm_kernel(
    const float* __restrict__ A, const __nv_bfloat16* __restrict__ Bh,
    const __nv_bfloat16* __restrict__ Bl, float* __restrict__ C,
    const int* __restrict__ row_map, int Mp,
    const float* __restrict__ epi_vec, int epi_mode)
{
    const int M = (Mp < 0) ? g_total_rows : Mp;
    const int gm0 = blockIdx.x * 128;
    if (gm0 >= M) return;
    extern __shared__ char sm[];
    const uint32_t sb = smem_u32(sm);
    const int tid = threadIdx.x, lane = tid & 31, wid = tid >> 5;
    const int wm = wid & 1, wn = wid >> 1;
    const int n0 = blockIdx.y * 128;

    const int alr = lane & 15;
    const int alc = (lane & 16) >> 1;
    const int blr = (lane & 7) | ((lane >> 1) & 8);
    const int blc = lane & 8;
    const uint32_t a_base = sb + AS_HI + (uint32_t)(((wm * 64 + alr) * 72 + alc) * 2);
    const uint32_t b_base = sb + BS_HI + (uint32_t)(((wn * 32 + blr) * 72 + blc) * 2);

    float c[4][4][4];
#pragma unroll
    for (int mt = 0; mt < 4; mt++)
#pragma unroll
        for (int nf = 0; nf < 4; nf++)
#pragma unroll
            for (int r = 0; r < 4; r++) c[mt][nf][r] = 0.f;

    for (int ch = 0; ch < 4; ch++) {
        const int k0 = ch * 64;
#pragma unroll
        for (int i = 0; i < 8; i++) {
            int idx = tid + i * 256;
            int m = idx >> 4, kq = idx & 15;
            float4 v = make_float4(0.f, 0.f, 0.f, 0.f);
            int gm = gm0 + m;
            if (gm < M) {
                int row = row_map ? row_map[gm] : gm;
                v = *(const float4*)&A[(size_t)row * DDIM + k0 + kq * 4];
            }
            __nv_bfloat162 h0, h1, l0, l1;
            h0.x = __float2bfloat16_rn(v.x); h0.y = __float2bfloat16_rn(v.y);
            h1.x = __float2bfloat16_rn(v.z); h1.y = __float2bfloat16_rn(v.w);
            l0.x = __float2bfloat16_rn(v.x - __bfloat162float(h0.x));
            l0.y = __float2bfloat16_rn(v.y - __bfloat162float(h0.y));
            l1.x = __float2bfloat16_rn(v.z - __bfloat162float(h1.x));
            l1.y = __float2bfloat16_rn(v.w - __bfloat162float(h1.y));
            uint2 hp = make_uint2(*(uint32_t*)&h0, *(uint32_t*)&h1);
            uint2 lp = make_uint2(*(uint32_t*)&l0, *(uint32_t*)&l1);
            *(uint2*)(sm + AS_HI + m * 144 + kq * 8) = hp;
            *(uint2*)(sm + AS_LO + m * 144 + kq * 8) = lp;
        }
#pragma unroll
        for (int i = 0; i < 4; i++) {
            int idx = tid + i * 256;
            int n = idx >> 3, k4 = idx & 7;
            *(float4*)(sm + BS_HI + n * 144 + k4 * 16) =
                *(const float4*)&Bh[(size_t)(n0 + n) * DDIM + k0 + k4 * 8];
            *(float4*)(sm + BS_LO + n * 144 + k4 * 16) =
                *(const float4*)&Bl[(size_t)(n0 + n) * DDIM + k0 + k4 * 8];
        }
        __syncthreads();

#pragma unroll
        for (int ks = 0; ks < 4; ks++) {
            uint32_t ah[4][4], al[4][4], bh[2][4], bl[2][4];
#pragma unroll
            for (int mt = 0; mt < 4; mt++)
                LDSM4(ah[mt], a_base + mt * 2304 + ks * 32);
#pragma unroll
            for (int nt = 0; nt < 2; nt++) {
                LDSM4(bh[nt], b_base + nt * 2304 + ks * 32);
                LDSM4(bl[nt], b_base + 18432u + nt * 2304 + ks * 32);
            }
#pragma unroll
            for (int mt = 0; mt < 4; mt++)
#pragma unroll
                for (int nf = 0; nf < 4; nf++) {
                    MMA_BF16(c[mt][nf], ah[mt], bh[nf >> 1][(nf & 1) * 2],
                             bh[nf >> 1][(nf & 1) * 2 + 1]);
                    MMA_BF16(c[mt][nf], ah[mt], bl[nf >> 1][(nf & 1) * 2],
                             bl[nf >> 1][(nf & 1) * 2 + 1]);
                }
#pragma unroll
            for (int mt = 0; mt < 4; mt++)
                LDSM4(al[mt], a_base + 18432u + mt * 2304 + ks * 32);
#pragma unroll
            for (int mt = 0; mt < 4; mt++)
#pragma unroll
                for (int nf = 0; nf < 4; nf++)
                    MMA_BF16(c[mt][nf], al[mt], bh[nf >> 1][(nf & 1) * 2],
                             bh[nf >> 1][(nf & 1) * 2 + 1]);
        }
        __syncthreads();
    }

    // epilogue via smem stage (pitch 132)
    float* stage = (float*)sm;
    const int gID = lane >> 2, tg = lane & 3;
    for (int mh = 0; mh < 2; mh++) {
        if (wm == mh) {
#pragma unroll
            for (int mt = 0; mt < 4; mt++)
#pragma unroll
                for (int nf = 0; nf < 4; nf++) {
                    int r = mt * 16 + gID;
                    int cc = wn * 32 + nf * 8 + tg * 2;
                    *(float2*)&stage[r * 132 + cc] =
                        make_float2(c[mt][nf][0], c[mt][nf][1]);
                    *(float2*)&stage[(r + 8) * 132 + cc] =
                        make_float2(c[mt][nf][2], c[mt][nf][3]);
                }
        }
        __syncthreads();
#pragma unroll
        for (int i = 0; i < 8; i++) {
            int idx = tid + i * 256;
            int r = idx >> 5, c4 = idx & 31;
            int grow = gm0 + mh * 64 + r;
            if (grow < M) {
                float4 x = *(float4*)&stage[r * 132 + c4 * 4];
                int n = n0 + c4 * 4;
                if (epi_mode == 1) {
                    float4 v = *(const float4*)&epi_vec[n];
                    x.x = tanhf(x.x + v.x); x.y = tanhf(x.y + v.y);
                    x.z = tanhf(x.z + v.z); x.w = tanhf(x.w + v.w);
                } else if (epi_mode == 2) {
                    float4 v = *(const float4*)&epi_vec[n];
                    x.x += v.x; x.y += v.y; x.z += v.z; x.w += v.w;
                }
                *(float4*)&C[(size_t)grow * DDIM + n] = x;
            }
        }
        __syncthreads();
    }
}

// ============ warp-per-doc fused pre + recurrence ============
__global__ void __launch_bounds__(256) recur_kernel(
    const float* __restrict__ sent, const float* __restrict__ bias,
    const int* __restrict__ doc_lens, int B, float* __restrict__ out)
{
    __shared__ float sA[LMAX];
    __shared__ float sR[32];
    const int tid = threadIdx.x, lane = tid & 31, wid = tid >> 5;
    if (tid < LMAX) sA[tid] = g_abs_vals[tid];
    if (tid < 32) sR[tid] = g_rel_vals[tid];
    __syncthreads();

    const int b = blockIdx.x * 8 + wid;
    if (b >= B) return;
    const int dl = doc_lens[b];
    const float dlf = (float)dl;
    const int off = g_offs[b];
    const float* hp = sent + (size_t)b * LMAX * DDIM + lane * 8;
    const float* gp = g_G + (size_t)off * DDIM + lane * 8;
    const float b0 = bias[0];

    float u[8];
    {
        const float* up = g_u + (size_t)b * DDIM + lane * 8;
        *(float4*)u = *(const float4*)up;
        *(float4*)(u + 4) = *(const float4*)(up + 4);
    }
    float s[8] = {0.f, 0.f, 0.f, 0.f, 0.f, 0.f, 0.f, 0.f};
    float h[8], g[8];
    *(float4*)h = *(const float4*)hp;
    *(float4*)(h + 4) = *(const float4*)(hp + 4);
    *(float4*)g = *(const float4*)gp;
    *(float4*)(g + 4) = *(const float4*)(gp + 4);

    for (int t = 0; t < dl; t++) {
        float hn[8] = {0, 0, 0, 0, 0, 0, 0, 0};
        float gn[8] = {0, 0, 0, 0, 0, 0, 0, 0};
        if (t + 1 < dl) {
            const float* hq = hp + (size_t)(t + 1) * DDIM;
            const float* gq = gp + (size_t)(t + 1) * DDIM;
            *(float4*)hn = *(const float4*)hq;
            *(float4*)(hn + 4) = *(const float4*)(hq + 4);
            *(float4*)gn = *(const float4*)gq;
            *(float4*)(gn + 4) = *(const float4*)(gq + 4);
        }
        float v = 0.f;
#pragma unroll
        for (int e = 0; e < 8; e++)
            v += h[e] * u[e] - g[e] * tanhf(s[e]);
#pragma unroll
        for (int st = 16; st; st >>= 1) v += __shfl_xor_sync(0xffffffffu, v, st);
        int ri = (int)rintf(__fdiv_rn((float)(t + 1) * 9.0f, dlf));
        float x = v + sA[t] + sR[ri] + b0;
        float p = __fdiv_rn(1.f, 1.f + expf(-x));
#pragma unroll
        for (int e = 0; e < 8; e++) s[e] = fmaf(p, h[e], s[e]);
        if (lane == 0) out[off + t] = p;
#pragma unroll
        for (int e = 0; e < 8; e++) { h[e] = hn[e]; g[e] = gn[e]; }
    }
}

// ======================= launch =======================
extern "C" void kernel_launch(void* const* d_in, const int* in_sizes, int n_in,
                              void* d_out, int out_size) {
    const float* sent      = (const float*)d_in[0];
    const float* fc_w      = (const float*)d_in[1];
    const float* fc_b      = (const float*)d_in[2];
    const float* w_content = (const float*)d_in[3];
    const float* W_sal     = (const float*)d_in[4];
    const float* W_nov     = (const float*)d_in[5];
    const float* abs_e     = (const float*)d_in[6];
    const float* rel_e     = (const float*)d_in[7];
    const float* w_abs     = (const float*)d_in[8];
    const float* w_rel     = (const float*)d_in[9];
    const float* bias      = (const float*)d_in[10];
    const int*   doc_lens  = (const int*)d_in[11];
    const int B = in_sizes[11];
    const int rows_max = B * LMAX;

    cudaFuncSetAttribute(gemm_kernel,
                         cudaFuncAttributeMaxDynamicSharedMemorySize, GSM_TOTAL);

    __nv_bfloat16 *W1h, *W1l, *W2h, *W2l, *W3h, *W3l;
    float *docs, *doc, *u, *G;
    int *rowmap;
    cudaGetSymbolAddress((void**)&W1h, g_W1h);
    cudaGetSymbolAddress((void**)&W1l, g_W1l);
    cudaGetSymbolAddress((void**)&W2h, g_W2h);
    cudaGetSymbolAddress((void**)&W2l, g_W2l);
    cudaGetSymbolAddress((void**)&W3h, g_W3h);
    cudaGetSymbolAddress((void**)&W3l, g_W3l);
    cudaGetSymbolAddress((void**)&docs, g_docs);
    cudaGetSymbolAddress((void**)&doc, g_doc);
    cudaGetSymbolAddress((void**)&u, g_u);
    cudaGetSymbolAddress((void**)&G, g_G);
    cudaGetSymbolAddress((void**)&rowmap, g_rowmap);

    scan_kernel<<<1, 256>>>(doc_lens, B, abs_e, rel_e, w_abs, w_rel);
    prep_kernel<<<dim3(256, 3), 256>>>(fc_w, W_sal, W_nov);
    rowmap_kernel<<<B, 128>>>(doc_lens);
    mean_kernel<<<B, 256>>>(sent, doc_lens);
    // doc = tanh(docs @ fc_w^T + fc_b)
    gemm_kernel<<<dim3((B + 127) / 128, 2), 256, GSM_TOTAL>>>(
        docs, W1h, W1l, doc, nullptr, B, fc_b, 1);
    // u = doc @ W_sal^T + w_content
    gemm_kernel<<<dim3((B + 127) / 128, 2), 256, GSM_TOTAL>>>(
        doc, W2h, W2l, u, nullptr, B, w_content, 2);
    // G = sent_valid @ W_nov (compacted rows)
    gemm_kernel<<<dim3((rows_max + 127) / 128, 2), 256, GSM_TOTAL>>>(
        sent, W3h, W3l, G, rowmap, -1, nullptr, 0);
    recur_kernel<<<(B + 7) / 8, 256>>>(sent, bias, doc_lens, B, (float*)d_out);
}

// round 5
// speedup vs baseline: 3.2790x; 1.1393x over previous
#include <cuda_runtime.h>
#include <cuda_bf16.h>
#include <math.h>
#include <cstdint>

#define B_MAX 2048
#define LMAX 100
#define DDIM 256
#define POS_DIM 50

__device__ int   g_offs[B_MAX];
__device__ int   g_perm[B_MAX];
__device__ int   g_total_rows;
__device__ int   g_rowmap[(size_t)B_MAX * LMAX];
__device__ float g_abs_vals[LMAX];
__device__ float g_rel_vals[32];
__device__ float g_docs[(size_t)B_MAX * DDIM];
__device__ float g_doc[(size_t)B_MAX * DDIM];
__device__ float g_u[(size_t)B_MAX * DDIM];
__device__ float g_G[(size_t)B_MAX * LMAX * DDIM];
__device__ __nv_bfloat16 g_W1h[DDIM * DDIM], g_W1l[DDIM * DDIM]; // fc_w
__device__ __nv_bfloat16 g_W2h[DDIM * DDIM], g_W2l[DDIM * DDIM]; // W_sal
__device__ __nv_bfloat16 g_W3h[DDIM * DDIM], g_W3l[DDIM * DDIM]; // W_nov^T

__device__ __forceinline__ uint32_t smem_u32(const void* p) {
    uint32_t a;
    asm("{ .reg .u64 t; cvta.to.shared.u64 t, %1; cvt.u32.u64 %0, t; }"
        : "=r"(a) : "l"(p));
    return a;
}
#define LDSM4(r, addr) \
    asm volatile("ldmatrix.sync.aligned.m8n8.x4.shared.b16 {%0,%1,%2,%3}, [%4];" \
        : "=r"((r)[0]), "=r"((r)[1]), "=r"((r)[2]), "=r"((r)[3]) : "r"(addr))
#define MMA_BF16(c, a, b0, b1) \
    asm volatile("mma.sync.aligned.m16n8k16.row.col.f32.bf16.bf16.f32 " \
        "{%0,%1,%2,%3},{%4,%5,%6,%7},{%8,%9},{%0,%1,%2,%3};" \
        : "+f"((c)[0]), "+f"((c)[1]), "+f"((c)[2]), "+f"((c)[3]) \
        : "r"((a)[0]), "r"((a)[1]), "r"((a)[2]), "r"((a)[3]), "r"(b0), "r"(b1))

// ============ scan: offsets, total, length-sort perm, position dots ============
__global__ void scan_kernel(const int* __restrict__ dl, int B,
                            const float* __restrict__ abs_e,
                            const float* __restrict__ rel_e,
                            const float* __restrict__ w_abs,
                            const float* __restrict__ w_rel) {
    __shared__ int sh[B_MAX];
    __shared__ int wsum[8];
    __shared__ int hist[LMAX + 1];
    __shared__ int hstart[LMAX + 1];
    int t = threadIdx.x;
    for (int i = t; i < B_MAX; i += 256) sh[i] = (i < B) ? dl[i] : 0;
    if (t <= LMAX) hist[t] = 0;
    __syncthreads();
    // exclusive prefix offsets
    int base = t * 8;
    int ex[8]; int run = 0;
#pragma unroll
    for (int k = 0; k < 8; k++) { ex[k] = run; run += sh[base + k]; }
    int lane = t & 31, w = t >> 5;
    int inc = run;
#pragma unroll
    for (int st = 1; st < 32; st <<= 1) {
        int x = __shfl_up_sync(0xffffffffu, inc, st);
        if (lane >= st) inc += x;
    }
    if (lane == 31) wsum[w] = inc;
    // histogram of lengths
    for (int i = t; i < B; i += 256) {
        int d = sh[i]; d = (d < 0) ? 0 : (d > LMAX ? LMAX : d);
        atomicAdd(&hist[d], 1);
    }
    __syncthreads();
    int wbase = 0;
    for (int i = 0; i < w; i++) wbase += wsum[i];
    int chunk_ex = wbase + inc - run;
#pragma unroll
    for (int k = 0; k < 8; k++)
        if (base + k < B) g_offs[base + k] = chunk_ex + ex[k];
    if (t == 0) {
        int tot = 0;
        for (int i = 0; i < 8; i++) tot += wsum[i];
        g_total_rows = tot;
        int running = 0;                     // descending-length start offsets
        for (int d = LMAX; d >= 0; d--) { hstart[d] = running; running += hist[d]; }
    }
    __syncthreads();
    for (int i = t; i < B; i += 256) {
        int d = sh[i]; d = (d < 0) ? 0 : (d > LMAX ? LMAX : d);
        int pos = atomicAdd(&hstart[d], 1);
        g_perm[pos] = i;
    }
    // abs/rel position scalars
    if (t < LMAX) {
        float a = 0.f;
        for (int i = 0; i < POS_DIM; i++) a += abs_e[t * POS_DIM + i] * w_abs[i];
        g_abs_vals[t] = a;
    } else if (t >= 128 && t < 153) {
        int s = t - 128;
        float a = 0.f;
        for (int i = 0; i < POS_DIM; i++) a += rel_e[s * POS_DIM + i] * w_rel[i];
        g_rel_vals[s] = a;
    }
}

// ============ weight prep: bf16 hi/lo, W_nov transposed ============
__global__ void prep_kernel(const float* __restrict__ fc_w,
                            const float* __restrict__ W_sal,
                            const float* __restrict__ W_nov) {
    int idx = blockIdx.x * 256 + threadIdx.x;
    int y = blockIdx.y;
    if (y == 0) {
        int n = idx >> 8, k = idx & 255;
        float w = W_nov[k * DDIM + n];
        __nv_bfloat16 h = __float2bfloat16_rn(w);
        g_W3h[n * DDIM + k] = h;
        g_W3l[n * DDIM + k] = __float2bfloat16_rn(w - __bfloat162float(h));
    } else if (y == 1) {
        float w = fc_w[idx];
        __nv_bfloat16 h = __float2bfloat16_rn(w);
        g_W1h[idx] = h;
        g_W1l[idx] = __float2bfloat16_rn(w - __bfloat162float(h));
    } else {
        float w = W_sal[idx];
        __nv_bfloat16 h = __float2bfloat16_rn(w);
        g_W2h[idx] = h;
        g_W2l[idx] = __float2bfloat16_rn(w - __bfloat162float(h));
    }
}

// ============ rowmap expand ============
__global__ void rowmap_kernel(const int* __restrict__ dl) {
    int b = blockIdx.x;
    int n = dl[b], off = g_offs[b];
    for (int t = threadIdx.x; t < n; t += 128)
        g_rowmap[off + t] = b * LMAX + t;
}

// ============ masked mean (float4, 4 rows in flight) ============
__global__ void __launch_bounds__(256) mean_kernel(const float* __restrict__ sent,
                                                   const int* __restrict__ dl) {
    __shared__ float4 part[4][64];
    int b = blockIdx.x, tid = threadIdx.x;
    int n = dl[b];
    int c4 = tid & 63, rq = tid >> 6;
    const float4* sp = (const float4*)(sent + (size_t)b * LMAX * DDIM);
    float4 a = make_float4(0.f, 0.f, 0.f, 0.f);
    for (int t = rq; t < n; t += 4) {
        float4 v = sp[t * 64 + c4];
        a.x += v.x; a.y += v.y; a.z += v.z; a.w += v.w;
    }
    part[rq][c4] = a;
    __syncthreads();
    if (tid < 64) {
        float4 r0 = part[0][tid], r1 = part[1][tid], r2 = part[2][tid], r3 = part[3][tid];
        float inv = __fdiv_rn(1.f, (float)n);
        float4 o;
        o.x = (r0.x + r1.x + r2.x + r3.x) * inv;
        o.y = (r0.y + r1.y + r2.y + r3.y) * inv;
        o.z = (r0.z + r1.z + r2.z + r3.z) * inv;
        o.w = (r0.w + r1.w + r2.w + r3.w) * inv;
        *(float4*)&g_docs[(size_t)b * DDIM + tid * 4] = o;
    }
}

// ============ HMMA GEMM: C = A @ W (3-pass bf16 split) ============
#define AS_HI 0
#define AS_LO 18432
#define BS_HI 36864
#define BS_LO 55296
#define GSM_TOTAL 73728

__global__ void __launch_bounds__(256, 2) gemm_kernel(
    const float* __restrict__ A, const __nv_bfloat16* __restrict__ Bh,
    const __nv_bfloat16* __restrict__ Bl, float* __restrict__ C,
    const int* __restrict__ row_map, int Mp,
    const float* __restrict__ epi_vec, int epi_mode)
{
    const int M = (Mp < 0) ? g_total_rows : Mp;
    const int gm0 = blockIdx.x * 128;
    if (gm0 >= M) return;
    extern __shared__ char sm[];
    const uint32_t sb = smem_u32(sm);
    const int tid = threadIdx.x, lane = tid & 31, wid = tid >> 5;
    const int wm = wid & 1, wn = wid >> 1;
    const int n0 = blockIdx.y * 128;

    const int alr = lane & 15;
    const int alc = (lane & 16) >> 1;
    const int blr = (lane & 7) | ((lane >> 1) & 8);
    const int blc = lane & 8;
    const uint32_t a_base = sb + AS_HI + (uint32_t)(((wm * 64 + alr) * 72 + alc) * 2);
    const uint32_t b_base = sb + BS_HI + (uint32_t)(((wn * 32 + blr) * 72 + blc) * 2);

    float c[4][4][4];
#pragma unroll
    for (int mt = 0; mt < 4; mt++)
#pragma unroll
        for (int nf = 0; nf < 4; nf++)
#pragma unroll
            for (int r = 0; r < 4; r++) c[mt][nf][r] = 0.f;

    for (int ch = 0; ch < 4; ch++) {
        const int k0 = ch * 64;
#pragma unroll
        for (int i = 0; i < 8; i++) {
            int idx = tid + i * 256;
            int m = idx >> 4, kq = idx & 15;
            float4 v = make_float4(0.f, 0.f, 0.f, 0.f);
            int gm = gm0 + m;
            if (gm < M) {
                int row = row_map ? row_map[gm] : gm;
                v = *(const float4*)&A[(size_t)row * DDIM + k0 + kq * 4];
            }
            __nv_bfloat162 h01 = __float22bfloat162_rn(make_float2(v.x, v.y));
            __nv_bfloat162 h23 = __float22bfloat162_rn(make_float2(v.z, v.w));
            float2 f01 = __bfloat1622float2(h01);
            float2 f23 = __bfloat1622float2(h23);
            __nv_bfloat162 l01 = __float22bfloat162_rn(make_float2(v.x - f01.x, v.y - f01.y));
            __nv_bfloat162 l23 = __float22bfloat162_rn(make_float2(v.z - f23.x, v.w - f23.y));
            uint2 hp = make_uint2(*(uint32_t*)&h01, *(uint32_t*)&h23);
            uint2 lp = make_uint2(*(uint32_t*)&l01, *(uint32_t*)&l23);
            *(uint2*)(sm + AS_HI + m * 144 + kq * 8) = hp;
            *(uint2*)(sm + AS_LO + m * 144 + kq * 8) = lp;
        }
#pragma unroll
        for (int i = 0; i < 4; i++) {
            int idx = tid + i * 256;
            int n = idx >> 3, k4 = idx & 7;
            *(float4*)(sm + BS_HI + n * 144 + k4 * 16) =
                *(const float4*)&Bh[(size_t)(n0 + n) * DDIM + k0 + k4 * 8];
            *(float4*)(sm + BS_LO + n * 144 + k4 * 16) =
                *(const float4*)&Bl[(size_t)(n0 + n) * DDIM + k0 + k4 * 8];
        }
        __syncthreads();

#pragma unroll
        for (int ks = 0; ks < 4; ks++) {
            uint32_t ah[4][4], al[4][4], bh[2][4], bl[2][4];
#pragma unroll
            for (int mt = 0; mt < 4; mt++)
                LDSM4(ah[mt], a_base + mt * 2304 + ks * 32);
#pragma unroll
            for (int nt = 0; nt < 2; nt++) {
                LDSM4(bh[nt], b_base + nt * 2304 + ks * 32);
                LDSM4(bl[nt], b_base + 18432u + nt * 2304 + ks * 32);
            }
#pragma unroll
            for (int mt = 0; mt < 4; mt++)
#pragma unroll
                for (int nf = 0; nf < 4; nf++) {
                    MMA_BF16(c[mt][nf], ah[mt], bh[nf >> 1][(nf & 1) * 2],
                             bh[nf >> 1][(nf & 1) * 2 + 1]);
                    MMA_BF16(c[mt][nf], ah[mt], bl[nf >> 1][(nf & 1) * 2],
                             bl[nf >> 1][(nf & 1) * 2 + 1]);
                }
#pragma unroll
            for (int mt = 0; mt < 4; mt++)
                LDSM4(al[mt], a_base + 18432u + mt * 2304 + ks * 32);
#pragma unroll
            for (int mt = 0; mt < 4; mt++)
#pragma unroll
                for (int nf = 0; nf < 4; nf++)
                    MMA_BF16(c[mt][nf], al[mt], bh[nf >> 1][(nf & 1) * 2],
                             bh[nf >> 1][(nf & 1) * 2 + 1]);
        }
        __syncthreads();
    }

    float* stage = (float*)sm;
    const int gID = lane >> 2, tg = lane & 3;
    for (int mh = 0; mh < 2; mh++) {
        if (wm == mh) {
#pragma unroll
            for (int mt = 0; mt < 4; mt++)
#pragma unroll
                for (int nf = 0; nf < 4; nf++) {
                    int r = mt * 16 + gID;
                    int cc = wn * 32 + nf * 8 + tg * 2;
                    *(float2*)&stage[r * 132 + cc] =
                        make_float2(c[mt][nf][0], c[mt][nf][1]);
                    *(float2*)&stage[(r + 8) * 132 + cc] =
                        make_float2(c[mt][nf][2], c[mt][nf][3]);
                }
        }
        __syncthreads();
#pragma unroll
        for (int i = 0; i < 8; i++) {
            int idx = tid + i * 256;
            int r = idx >> 5, c4 = idx & 31;
            int grow = gm0 + mh * 64 + r;
            if (grow < M) {
                float4 x = *(float4*)&stage[r * 132 + c4 * 4];
                int n = n0 + c4 * 4;
                if (epi_mode == 1) {
                    float4 v = *(const float4*)&epi_vec[n];
                    x.x = tanhf(x.x + v.x); x.y = tanhf(x.y + v.y);
                    x.z = tanhf(x.z + v.z); x.w = tanhf(x.w + v.w);
                } else if (epi_mode == 2) {
                    float4 v = *(const float4*)&epi_vec[n];
                    x.x += v.x; x.y += v.y; x.z += v.z; x.w += v.w;
                }
                *(float4*)&C[(size_t)grow * DDIM + n] = x;
            }
        }
        __syncthreads();
    }
}

// ============ fast tanh: 1 - 2/(e^{2x}+1), abs err ~1e-6 ============
__device__ __forceinline__ float fast_tanh(float x) {
    float e = __expf(2.f * x);
    return 1.f - __fdividef(2.f, e + 1.f);
}

// ============ warp-per-doc fused pre + recurrence (length-sorted) ============
__global__ void __launch_bounds__(256) recur_kernel(
    const float* __restrict__ sent, const float* __restrict__ bias,
    const int* __restrict__ doc_lens, int B, float* __restrict__ out)
{
    __shared__ float sA[LMAX];
    __shared__ float sR[32];
    const int tid = threadIdx.x, lane = tid & 31, wid = tid >> 5;
    if (tid < LMAX) sA[tid] = g_abs_vals[tid];
    if (tid < 32) sR[tid] = g_rel_vals[tid];
    __syncthreads();

    const int gid = blockIdx.x * 8 + wid;
    if (gid >= B) return;
    const int b = g_perm[gid];
    const int dl = doc_lens[b];
    const float dlf = (float)dl;
    const int off = g_offs[b];
    const float* hp = sent + (size_t)b * LMAX * DDIM + lane * 8;
    const float* gp = g_G + (size_t)off * DDIM + lane * 8;
    const float b0 = bias[0];

    float u[8];
    {
        const float* up = g_u + (size_t)b * DDIM + lane * 8;
        *(float4*)u = *(const float4*)up;
        *(float4*)(u + 4) = *(const float4*)(up + 4);
    }
    float s[8] = {0.f, 0.f, 0.f, 0.f, 0.f, 0.f, 0.f, 0.f};
    float h[8], g[8];
    *(float4*)h = *(const float4*)hp;
    *(float4*)(h + 4) = *(const float4*)(hp + 4);
    *(float4*)g = *(const float4*)gp;
    *(float4*)(g + 4) = *(const float4*)(gp + 4);

    for (int t = 0; t < dl; t++) {
        float hn[8] = {0, 0, 0, 0, 0, 0, 0, 0};
        float gn[8] = {0, 0, 0, 0, 0, 0, 0, 0};
        if (t + 1 < dl) {
            const float* hq = hp + (size_t)(t + 1) * DDIM;
            const float* gq = gp + (size_t)(t + 1) * DDIM;
            *(float4*)hn = *(const float4*)hq;
            *(float4*)(hn + 4) = *(const float4*)(hq + 4);
            *(float4*)gn = *(const float4*)gq;
            *(float4*)(gn + 4) = *(const float4*)(gq + 4);
        }
        float v = 0.f;
#pragma unroll
        for (int e = 0; e < 8; e++)
            v += h[e] * u[e] - g[e] * fast_tanh(s[e]);
#pragma unroll
        for (int st = 16; st; st >>= 1) v += __shfl_xor_sync(0xffffffffu, v, st);
        int ri = (int)rintf(__fdiv_rn((float)(t + 1) * 9.0f, dlf));
        float x = v + sA[t] + sR[ri] + b0;
        float p = __fdiv_rn(1.f, 1.f + expf(-x));
#pragma unroll
        for (int e = 0; e < 8; e++) s[e] = fmaf(p, h[e], s[e]);
        if (lane == 0) out[off + t] = p;
#pragma unroll
        for (int e = 0; e < 8; e++) { h[e] = hn[e]; g[e] = gn[e]; }
    }
}

// ======================= launch =======================
extern "C" void kernel_launch(void* const* d_in, const int* in_sizes, int n_in,
                              void* d_out, int out_size) {
    const float* sent      = (const float*)d_in[0];
    const float* fc_w      = (const float*)d_in[1];
    const float* fc_b      = (const float*)d_in[2];
    const float* w_content = (const float*)d_in[3];
    const float* W_sal     = (const float*)d_in[4];
    const float* W_nov     = (const float*)d_in[5];
    const float* abs_e     = (const float*)d_in[6];
    const float* rel_e     = (const float*)d_in[7];
    const float* w_abs     = (const float*)d_in[8];
    const float* w_rel     = (const float*)d_in[9];
    const float* bias      = (const float*)d_in[10];
    const int*   doc_lens  = (const int*)d_in[11];
    const int B = in_sizes[11];
    const int rows_max = B * LMAX;

    cudaFuncSetAttribute(gemm_kernel,
                         cudaFuncAttributeMaxDynamicSharedMemorySize, GSM_TOTAL);

    __nv_bfloat16 *W1h, *W1l, *W2h, *W2l, *W3h, *W3l;
    float *docs, *doc, *u, *G;
    int *rowmap;
    cudaGetSymbolAddress((void**)&W1h, g_W1h);
    cudaGetSymbolAddress((void**)&W1l, g_W1l);
    cudaGetSymbolAddress((void**)&W2h, g_W2h);
    cudaGetSymbolAddress((void**)&W2l, g_W2l);
    cudaGetSymbolAddress((void**)&W3h, g_W3h);
    cudaGetSymbolAddress((void**)&W3l, g_W3l);
    cudaGetSymbolAddress((void**)&docs, g_docs);
    cudaGetSymbolAddress((void**)&doc, g_doc);
    cudaGetSymbolAddress((void**)&u, g_u);
    cudaGetSymbolAddress((void**)&G, g_G);
    cudaGetSymbolAddress((void**)&rowmap, g_rowmap);

    // persistent side stream + events (host objects only; no device memory)
    static cudaStream_t s_side = nullptr;
    static cudaEvent_t ev_fork = nullptr, ev_join = nullptr;
    if (!s_side) {
        cudaStreamCreateWithFlags(&s_side, cudaStreamNonBlocking);
        cudaEventCreateWithFlags(&ev_fork, cudaEventDisableTiming);
        cudaEventCreateWithFlags(&ev_join, cudaEventDisableTiming);
    }

    // main stream: scan, prep, rowmap, gemm3 (big)
    scan_kernel<<<1, 256>>>(doc_lens, B, abs_e, rel_e, w_abs, w_rel);
    prep_kernel<<<dim3(256, 3), 256>>>(fc_w, W_sal, W_nov);
    rowmap_kernel<<<B, 128>>>(doc_lens);

    cudaEventRecord(ev_fork, 0);
    cudaStreamWaitEvent(s_side, ev_fork, 0);

    // side stream: mean -> doc -> u (hidden under gemm3)
    mean_kernel<<<B, 256, 0, s_side>>>(sent, doc_lens);
    gemm_kernel<<<dim3((B + 127) / 128, 2), 256, GSM_TOTAL, s_side>>>(
        docs, W1h, W1l, doc, nullptr, B, fc_b, 1);
    gemm_kernel<<<dim3((B + 127) / 128, 2), 256, GSM_TOTAL, s_side>>>(
        doc, W2h, W2l, u, nullptr, B, w_content, 2);
    cudaEventRecord(ev_join, s_side);

    // main stream: G = sent_valid @ W_nov
    gemm_kernel<<<dim3((rows_max + 127) / 128, 2), 256, GSM_TOTAL>>>(
        sent, W3h, W3l, G, rowmap, -1, nullptr, 0);

    cudaStreamWaitEvent(0, ev_join, 0);
    recur_kernel<<<(B + 7) / 8, 256>>>(sent, bias, doc_lens, B, (float*)d_out);
}

// round 7
// speedup vs baseline: 3.3716x; 1.0282x over previous
#include <cuda_runtime.h>
#include <cuda_bf16.h>
#include <math.h>
#include <cstdint>

#define B_MAX 2048
#define LMAX 100
#define DDIM 256
#define POS_DIM 50

__device__ int   g_offs[B_MAX];
__device__ int   g_perm[B_MAX];
__device__ int   g_total_rows;
__device__ int   g_rowmap[(size_t)B_MAX * LMAX];
__device__ float g_abs_vals[LMAX];
__device__ float g_rel_vals[32];
__device__ float g_docs[(size_t)B_MAX * DDIM];
__device__ float g_doc[(size_t)B_MAX * DDIM];
__device__ float g_u[(size_t)B_MAX * DDIM];
__device__ float g_G[(size_t)B_MAX * LMAX * DDIM];
__device__ __nv_bfloat16 g_W1h[DDIM * DDIM], g_W1l[DDIM * DDIM]; // fc_w
__device__ __nv_bfloat16 g_W2h[DDIM * DDIM], g_W2l[DDIM * DDIM]; // W_sal
__device__ __nv_bfloat16 g_W3h[DDIM * DDIM], g_W3l[DDIM * DDIM]; // W_nov^T

__device__ __forceinline__ uint32_t smem_u32(const void* p) {
    uint32_t a;
    asm("{ .reg .u64 t; cvta.to.shared.u64 t, %1; cvt.u32.u64 %0, t; }"
        : "=r"(a) : "l"(p));
    return a;
}
#define LDSM4(r, addr) \
    asm volatile("ldmatrix.sync.aligned.m8n8.x4.shared.b16 {%0,%1,%2,%3}, [%4];" \
        : "=r"((r)[0]), "=r"((r)[1]), "=r"((r)[2]), "=r"((r)[3]) : "r"(addr))
#define MMA_BF16(c, a, b0, b1) \
    asm volatile("mma.sync.aligned.m16n8k16.row.col.f32.bf16.bf16.f32 " \
        "{%0,%1,%2,%3},{%4,%5,%6,%7},{%8,%9},{%0,%1,%2,%3};" \
        : "+f"((c)[0]), "+f"((c)[1]), "+f"((c)[2]), "+f"((c)[3]) \
        : "r"((a)[0]), "r"((a)[1]), "r"((a)[2]), "r"((a)[3]), "r"(b0), "r"(b1))

// ============ scan: offsets, total, length-sort perm, position dots ============
__global__ void scan_kernel(const int* __restrict__ dl, int B,
                            const float* __restrict__ abs_e,
                            const float* __restrict__ rel_e,
                            const float* __restrict__ w_abs,
                            const float* __restrict__ w_rel) {
    __shared__ int sh[B_MAX];
    __shared__ int wsum[8];
    __shared__ int hist[LMAX + 1];
    __shared__ int hstart[LMAX + 1];
    int t = threadIdx.x;
    for (int i = t; i < B_MAX; i += 256) sh[i] = (i < B) ? dl[i] : 0;
    if (t <= LMAX) hist[t] = 0;
    __syncthreads();
    int base = t * 8;
    int ex[8]; int run = 0;
#pragma unroll
    for (int k = 0; k < 8; k++) { ex[k] = run; run += sh[base + k]; }
    int lane = t & 31, w = t >> 5;
    int inc = run;
#pragma unroll
    for (int st = 1; st < 32; st <<= 1) {
        int x = __shfl_up_sync(0xffffffffu, inc, st);
        if (lane >= st) inc += x;
    }
    if (lane == 31) wsum[w] = inc;
    for (int i = t; i < B; i += 256) {
        int d = sh[i]; d = (d < 0) ? 0 : (d > LMAX ? LMAX : d);
        atomicAdd(&hist[d], 1);
    }
    __syncthreads();
    int wbase = 0;
    for (int i = 0; i < w; i++) wbase += wsum[i];
    int chunk_ex = wbase + inc - run;
#pragma unroll
    for (int k = 0; k < 8; k++)
        if (base + k < B) g_offs[base + k] = chunk_ex + ex[k];
    if (t == 0) {
        int tot = 0;
        for (int i = 0; i < 8; i++) tot += wsum[i];
        g_total_rows = tot;
        int running = 0;
        for (int d = LMAX; d >= 0; d--) { hstart[d] = running; running += hist[d]; }
    }
    __syncthreads();
    for (int i = t; i < B; i += 256) {
        int d = sh[i]; d = (d < 0) ? 0 : (d > LMAX ? LMAX : d);
        int pos = atomicAdd(&hstart[d], 1);
        g_perm[pos] = i;
    }
    if (t < LMAX) {
        float a = 0.f;
        for (int i = 0; i < POS_DIM; i++) a += abs_e[t * POS_DIM + i] * w_abs[i];
        g_abs_vals[t] = a;
    } else if (t >= 128 && t < 153) {
        int s = t - 128;
        float a = 0.f;
        for (int i = 0; i < POS_DIM; i++) a += rel_e[s * POS_DIM + i] * w_rel[i];
        g_rel_vals[s] = a;
    }
}

// ============ weight prep: bf16 hi/lo, W_nov transposed ============
__global__ void prep_kernel(const float* __restrict__ fc_w,
                            const float* __restrict__ W_sal,
                            const float* __restrict__ W_nov) {
    int idx = blockIdx.x * 256 + threadIdx.x;
    int y = blockIdx.y;
    if (y == 0) {
        int n = idx >> 8, k = idx & 255;
        float w = W_nov[k * DDIM + n];
        __nv_bfloat16 h = __float2bfloat16_rn(w);
        g_W3h[n * DDIM + k] = h;
        g_W3l[n * DDIM + k] = __float2bfloat16_rn(w - __bfloat162float(h));
    } else if (y == 1) {
        float w = fc_w[idx];
        __nv_bfloat16 h = __float2bfloat16_rn(w);
        g_W1h[idx] = h;
        g_W1l[idx] = __float2bfloat16_rn(w - __bfloat162float(h));
    } else {
        float w = W_sal[idx];
        __nv_bfloat16 h = __float2bfloat16_rn(w);
        g_W2h[idx] = h;
        g_W2l[idx] = __float2bfloat16_rn(w - __bfloat162float(h));
    }
}

// ============ rowmap expand ============
__global__ void rowmap_kernel(const int* __restrict__ dl) {
    int b = blockIdx.x;
    int n = dl[b], off = g_offs[b];
    for (int t = threadIdx.x; t < n; t += 128)
        g_rowmap[off + t] = b * LMAX + t;
}

// ============ masked mean (float4, 4 rows in flight) ============
__global__ void __launch_bounds__(256) mean_kernel(const float* __restrict__ sent,
                                                   const int* __restrict__ dl) {
    __shared__ float4 part[4][64];
    int b = blockIdx.x, tid = threadIdx.x;
    int n = dl[b];
    int c4 = tid & 63, rq = tid >> 6;
    const float4* sp = (const float4*)(sent + (size_t)b * LMAX * DDIM);
    float4 a = make_float4(0.f, 0.f, 0.f, 0.f);
    for (int t = rq; t < n; t += 4) {
        float4 v = sp[t * 64 + c4];
        a.x += v.x; a.y += v.y; a.z += v.z; a.w += v.w;
    }
    part[rq][c4] = a;
    __syncthreads();
    if (tid < 64) {
        float4 r0 = part[0][tid], r1 = part[1][tid], r2 = part[2][tid], r3 = part[3][tid];
        float inv = __fdiv_rn(1.f, (float)n);
        float4 o;
        o.x = (r0.x + r1.x + r2.x + r3.x) * inv;
        o.y = (r0.y + r1.y + r2.y + r3.y) * inv;
        o.z = (r0.z + r1.z + r2.z + r3.z) * inv;
        o.w = (r0.w + r1.w + r2.w + r3.w) * inv;
        *(float4*)&g_docs[(size_t)b * DDIM + tid * 4] = o;
    }
}

// ============ small HMMA GEMM (doc / u): C = A @ W, 128x128 tiles ============
#define AS_HI 0
#define AS_LO 18432
#define BS_HI 36864
#define BS_LO 55296
#define GSM_TOTAL 73728

__global__ void __launch_bounds__(256, 2) gemm_kernel(
    const float* __restrict__ A, const __nv_bfloat16* __restrict__ Bh,
    const __nv_bfloat16* __restrict__ Bl, float* __restrict__ C, int M,
    const float* __restrict__ epi_vec, int epi_mode)
{
    const int gm0 = blockIdx.x * 128;
    if (gm0 >= M) return;
    extern __shared__ char sm[];
    const uint32_t sb = smem_u32(sm);
    const int tid = threadIdx.x, lane = tid & 31, wid = tid >> 5;
    const int wm = wid & 1, wn = wid >> 1;
    const int n0 = blockIdx.y * 128;

    const int alr = lane & 15;
    const int alc = (lane & 16) >> 1;
    const int blr = (lane & 7) | ((lane >> 1) & 8);
    const int blc = lane & 8;
    const uint32_t a_base = sb + AS_HI + (uint32_t)(((wm * 64 + alr) * 72 + alc) * 2);
    const uint32_t b_base = sb + BS_HI + (uint32_t)(((wn * 32 + blr) * 72 + blc) * 2);

    float c[4][4][4];
#pragma unroll
    for (int mt = 0; mt < 4; mt++)
#pragma unroll
        for (int nf = 0; nf < 4; nf++)
#pragma unroll
            for (int r = 0; r < 4; r++) c[mt][nf][r] = 0.f;

    for (int ch = 0; ch < 4; ch++) {
        const int k0 = ch * 64;
#pragma unroll
        for (int i = 0; i < 8; i++) {
            int idx = tid + i * 256;
            int m = idx >> 4, kq = idx & 15;
            float4 v = make_float4(0.f, 0.f, 0.f, 0.f);
            int gm = gm0 + m;
            if (gm < M)
                v = *(const float4*)&A[(size_t)gm * DDIM + k0 + kq * 4];
            __nv_bfloat162 h01 = __float22bfloat162_rn(make_float2(v.x, v.y));
            __nv_bfloat162 h23 = __float22bfloat162_rn(make_float2(v.z, v.w));
            float2 f01 = __bfloat1622float2(h01);
            float2 f23 = __bfloat1622float2(h23);
            __nv_bfloat162 l01 = __float22bfloat162_rn(make_float2(v.x - f01.x, v.y - f01.y));
            __nv_bfloat162 l23 = __float22bfloat162_rn(make_float2(v.z - f23.x, v.w - f23.y));
            uint2 hp = make_uint2(*(uint32_t*)&h01, *(uint32_t*)&h23);
            uint2 lp = make_uint2(*(uint32_t*)&l01, *(uint32_t*)&l23);
            *(uint2*)(sm + AS_HI + m * 144 + kq * 8) = hp;
            *(uint2*)(sm + AS_LO + m * 144 + kq * 8) = lp;
        }
#pragma unroll
        for (int i = 0; i < 4; i++) {
            int idx = tid + i * 256;
            int n = idx >> 3, k4 = idx & 7;
            *(float4*)(sm + BS_HI + n * 144 + k4 * 16) =
                *(const float4*)&Bh[(size_t)(n0 + n) * DDIM + k0 + k4 * 8];
            *(float4*)(sm + BS_LO + n * 144 + k4 * 16) =
                *(const float4*)&Bl[(size_t)(n0 + n) * DDIM + k0 + k4 * 8];
        }
        __syncthreads();
#pragma unroll
        for (int ks = 0; ks < 4; ks++) {
            uint32_t ah[4][4], al[4][4], bh[2][4], bl[2][4];
#pragma unroll
            for (int mt = 0; mt < 4; mt++)
                LDSM4(ah[mt], a_base + mt * 2304 + ks * 32);
#pragma unroll
            for (int nt = 0; nt < 2; nt++) {
                LDSM4(bh[nt], b_base + nt * 2304 + ks * 32);
                LDSM4(bl[nt], b_base + 18432u + nt * 2304 + ks * 32);
            }
#pragma unroll
            for (int mt = 0; mt < 4; mt++)
#pragma unroll
                for (int nf = 0; nf < 4; nf++) {
                    MMA_BF16(c[mt][nf], ah[mt], bh[nf >> 1][(nf & 1) * 2],
                             bh[nf >> 1][(nf & 1) * 2 + 1]);
                    MMA_BF16(c[mt][nf], ah[mt], bl[nf >> 1][(nf & 1) * 2],
                             bl[nf >> 1][(nf & 1) * 2 + 1]);
                }
#pragma unroll
            for (int mt = 0; mt < 4; mt++)
                LDSM4(al[mt], a_base + 18432u + mt * 2304 + ks * 32);
#pragma unroll
            for (int mt = 0; mt < 4; mt++)
#pragma unroll
                for (int nf = 0; nf < 4; nf++)
                    MMA_BF16(c[mt][nf], al[mt], bh[nf >> 1][(nf & 1) * 2],
                             bh[nf >> 1][(nf & 1) * 2 + 1]);
        }
        __syncthreads();
    }

    float* stage = (float*)sm;
    const int gID = lane >> 2, tg = lane & 3;
    for (int mh = 0; mh < 2; mh++) {
        if (wm == mh) {
#pragma unroll
            for (int mt = 0; mt < 4; mt++)
#pragma unroll
                for (int nf = 0; nf < 4; nf++) {
                    int r = mt * 16 + gID;
                    int cc = wn * 32 + nf * 8 + tg * 2;
                    *(float2*)&stage[r * 132 + cc] =
                        make_float2(c[mt][nf][0], c[mt][nf][1]);
                    *(float2*)&stage[(r + 8) * 132 + cc] =
                        make_float2(c[mt][nf][2], c[mt][nf][3]);
                }
        }
        __syncthreads();
#pragma unroll
        for (int i = 0; i < 8; i++) {
            int idx = tid + i * 256;
            int r = idx >> 5, c4 = idx & 31;
            int grow = gm0 + mh * 64 + r;
            if (grow < M) {
                float4 x = *(float4*)&stage[r * 132 + c4 * 4];
                int n = n0 + c4 * 4;
                if (epi_mode == 1) {
                    float4 v = *(const float4*)&epi_vec[n];
                    x.x = tanhf(x.x + v.x); x.y = tanhf(x.y + v.y);
                    x.z = tanhf(x.z + v.z); x.w = tanhf(x.w + v.w);
                } else {
                    float4 v = *(const float4*)&epi_vec[n];
                    x.x += v.x; x.y += v.y; x.z += v.z; x.w += v.w;
                }
                *(float4*)&C[(size_t)grow * DDIM + n] = x;
            }
        }
        __syncthreads();
    }
}

// ============ big GEMM (A-persistent): G = sent_valid @ W_nov ============
#define A3_HI 0
#define A3_LO 33792
#define B3_HI 67584
#define B3_LO 86016
#define GSM3_TOTAL 104448

__global__ void __launch_bounds__(256, 2) gemm3_kernel(
    const float* __restrict__ A, const __nv_bfloat16* __restrict__ Bh,
    const __nv_bfloat16* __restrict__ Bl, float* __restrict__ C,
    const int* __restrict__ row_map)
{
    const int M = g_total_rows;
    const int gm0 = blockIdx.x * 64;
    if (gm0 >= M) return;
    extern __shared__ char sm[];
    const uint32_t sb = smem_u32(sm);
    const int tid = threadIdx.x, lane = tid & 31, wid = tid >> 5;
    const int wm = wid & 1, wn = wid >> 1;    // 2(M) x 4(N) warps

    // stage A once: 64 rows x 256 cols fp32 -> bf16 hi/lo, pitch 264 bf16
#pragma unroll
    for (int i = 0; i < 16; i++) {
        int idx = tid + i * 256;
        int m = idx >> 6, kq = idx & 63;
        float4 v = make_float4(0.f, 0.f, 0.f, 0.f);
        int gm = gm0 + m;
        if (gm < M)
            v = *(const float4*)&A[(size_t)row_map[gm] * DDIM + kq * 4];
        __nv_bfloat162 h01 = __float22bfloat162_rn(make_float2(v.x, v.y));
        __nv_bfloat162 h23 = __float22bfloat162_rn(make_float2(v.z, v.w));
        float2 f01 = __bfloat1622float2(h01);
        float2 f23 = __bfloat1622float2(h23);
        __nv_bfloat162 l01 = __float22bfloat162_rn(make_float2(v.x - f01.x, v.y - f01.y));
        __nv_bfloat162 l23 = __float22bfloat162_rn(make_float2(v.z - f23.x, v.w - f23.y));
        uint2 hp = make_uint2(*(uint32_t*)&h01, *(uint32_t*)&h23);
        uint2 lp = make_uint2(*(uint32_t*)&l01, *(uint32_t*)&l23);
        *(uint2*)(sm + A3_HI + m * 528 + kq * 8) = hp;
        *(uint2*)(sm + A3_LO + m * 528 + kq * 8) = lp;
    }

    const int alr = lane & 15;
    const int alc = (lane & 16) >> 1;
    const int blr = (lane & 7) | ((lane >> 1) & 8);
    const int blc = lane & 8;
    const uint32_t a_base = sb + A3_HI + (uint32_t)((wm * 32 + alr) * 528 + alc * 2);
    const uint32_t b_base = sb + B3_HI + (uint32_t)((wn * 32 + blr) * 144 + blc * 2);

    float c[2][4][4];
    const int gID = lane >> 2, tg = lane & 3;

    for (int nh = 0; nh < 2; nh++) {
#pragma unroll
        for (int mt = 0; mt < 2; mt++)
#pragma unroll
            for (int nf = 0; nf < 4; nf++)
#pragma unroll
                for (int r = 0; r < 4; r++) c[mt][nf][r] = 0.f;

        for (int ch = 0; ch < 4; ch++) {
            const int k0 = ch * 64;
            __syncthreads();
#pragma unroll
            for (int i = 0; i < 4; i++) {
                int idx = tid + i * 256;
                int n = idx >> 3, k4 = idx & 7;
                *(float4*)(sm + B3_HI + n * 144 + k4 * 16) =
                    *(const float4*)&Bh[(size_t)(nh * 128 + n) * DDIM + k0 + k4 * 8];
                *(float4*)(sm + B3_LO + n * 144 + k4 * 16) =
                    *(const float4*)&Bl[(size_t)(nh * 128 + n) * DDIM + k0 + k4 * 8];
            }
            __syncthreads();
#pragma unroll
            for (int ks = 0; ks < 4; ks++) {
                const uint32_t ka = (uint32_t)((k0 + ks * 16) * 2);
                uint32_t ah[2][4], al[2][4], bh[2][4], bl[2][4];
#pragma unroll
                for (int mt = 0; mt < 2; mt++) {
                    LDSM4(ah[mt], a_base + mt * 8448 + ka);
                    LDSM4(al[mt], a_base + 33792u + mt * 8448 + ka);
                }
#pragma unroll
                for (int nt = 0; nt < 2; nt++) {
                    LDSM4(bh[nt], b_base + nt * 2304 + ks * 32);
                    LDSM4(bl[nt], b_base + 18432u + nt * 2304 + ks * 32);
                }
#pragma unroll
                for (int mt = 0; mt < 2; mt++)
#pragma unroll
                    for (int nf = 0; nf < 4; nf++) {
                        MMA_BF16(c[mt][nf], ah[mt], bh[nf >> 1][(nf & 1) * 2],
                                 bh[nf >> 1][(nf & 1) * 2 + 1]);
                        MMA_BF16(c[mt][nf], ah[mt], bl[nf >> 1][(nf & 1) * 2],
                                 bl[nf >> 1][(nf & 1) * 2 + 1]);
                        MMA_BF16(c[mt][nf], al[mt], bh[nf >> 1][(nf & 1) * 2],
                                 bh[nf >> 1][(nf & 1) * 2 + 1]);
                    }
            }
        }

        __syncthreads();
        float* stage = (float*)(sm + B3_HI);
#pragma unroll
        for (int mt = 0; mt < 2; mt++)
#pragma unroll
            for (int nf = 0; nf < 4; nf++) {
                int r = wm * 32 + mt * 16 + gID;
                int cc = wn * 32 + nf * 8 + tg * 2;
                *(float2*)&stage[r * 132 + cc] =
                    make_float2(c[mt][nf][0], c[mt][nf][1]);
                *(float2*)&stage[(r + 8) * 132 + cc] =
                    make_float2(c[mt][nf][2], c[mt][nf][3]);
            }
        __syncthreads();
#pragma unroll
        for (int i = 0; i < 8; i++) {
            int idx = tid + i * 256;
            int r = idx >> 5, c4 = idx & 31;
            int grow = gm0 + r;
            if (grow < M)
                *(float4*)&C[(size_t)grow * DDIM + nh * 128 + c4 * 4] =
                    *(float4*)&stage[r * 132 + c4 * 4];
        }
    }
}

// ============ fast tanh: 1 - 2/(e^{2x}+1) ============
__device__ __forceinline__ float fast_tanh(float x) {
    float e = __expf(2.f * x);
    return 1.f - __fdividef(2.f, e + 1.f);
}

// ============ warp-per-doc fused pre + recurrence (length-sorted) ============
__global__ void __launch_bounds__(256) recur_kernel(
    const float* __restrict__ sent, const float* __restrict__ bias,
    const int* __restrict__ doc_lens, int B, float* __restrict__ out)
{
    __shared__ float sA[LMAX];
    __shared__ float sR[32];
    const int tid = threadIdx.x, lane = tid & 31, wid = tid >> 5;
    if (tid < LMAX) sA[tid] = g_abs_vals[tid];
    if (tid < 32) sR[tid] = g_rel_vals[tid];
    __syncthreads();

    const int gid = blockIdx.x * 8 + wid;
    if (gid >= B) return;
    const int b = g_perm[gid];
    const int dl = doc_lens[b];
    const float dlf = (float)dl;
    const int off = g_offs[b];
    const float* hp = sent + (size_t)b * LMAX * DDIM + lane * 8;
    const float* gp = g_G + (size_t)off * DDIM + lane * 8;
    const float b0 = bias[0];

    float u[8];
    {
        const float* up = g_u + (size_t)b * DDIM + lane * 8;
        *(float4*)u = *(const float4*)up;
        *(float4*)(u + 4) = *(const float4*)(up + 4);
    }
    float s[8] = {0.f, 0.f, 0.f, 0.f, 0.f, 0.f, 0.f, 0.f};
    float h[8], g[8];
    *(float4*)h = *(const float4*)hp;
    *(float4*)(h + 4) = *(const float4*)(hp + 4);
    *(float4*)g = *(const float4*)gp;
    *(float4*)(g + 4) = *(const float4*)(gp + 4);

    for (int t = 0; t < dl; t++) {
        float hn[8] = {0, 0, 0, 0, 0, 0, 0, 0};
        float gn[8] = {0, 0, 0, 0, 0, 0, 0, 0};
        if (t + 1 < dl) {
            const float* hq = hp + (size_t)(t + 1) * DDIM;
            const float* gq = gp + (size_t)(t + 1) * DDIM;
            *(float4*)hn = *(const float4*)hq;
            *(float4*)(hn + 4) = *(const float4*)(hq + 4);
            *(float4*)gn = *(const float4*)gq;
            *(float4*)(gn + 4) = *(const float4*)(gq + 4);
        }
        float v0 = 0.f, v1 = 0.f;
#pragma unroll
        for (int e = 0; e < 4; e++)
            v0 += h[e] * u[e] - g[e] * fast_tanh(s[e]);
#pragma unroll
        for (int e = 4; e < 8; e++)
            v1 += h[e] * u[e] - g[e] * fast_tanh(s[e]);
        float v = v0 + v1;
#pragma unroll
        for (int st = 16; st; st >>= 1) v += __shfl_xor_sync(0xffffffffu, v, st);
        int ri = (int)rintf(__fdiv_rn((float)(t + 1) * 9.0f, dlf));
        float x = v + sA[t] + sR[ri] + b0;
        float p = __fdividef(1.f, 1.f + __expf(-x));
#pragma unroll
        for (int e = 0; e < 8; e++) s[e] = fmaf(p, h[e], s[e]);
        if (lane == 0) out[off + t] = p;
#pragma unroll
        for (int e = 0; e < 8; e++) { h[e] = hn[e]; g[e] = gn[e]; }
    }
}

// ======================= launch =======================
extern "C" void kernel_launch(void* const* d_in, const int* in_sizes, int n_in,
                              void* d_out, int out_size) {
    const float* sent      = (const float*)d_in[0];
    const float* fc_w      = (const float*)d_in[1];
    const float* fc_b      = (const float*)d_in[2];
    const float* w_content = (const float*)d_in[3];
    const float* W_sal     = (const float*)d_in[4];
    const float* W_nov     = (const float*)d_in[5];
    const float* abs_e     = (const float*)d_in[6];
    const float* rel_e     = (const float*)d_in[7];
    const float* w_abs     = (const float*)d_in[8];
    const float* w_rel     = (const float*)d_in[9];
    const float* bias      = (const float*)d_in[10];
    const int*   doc_lens  = (const int*)d_in[11];
    const int B = in_sizes[11];
    const int rows_max = B * LMAX;

    cudaFuncSetAttribute(gemm_kernel,
                         cudaFuncAttributeMaxDynamicSharedMemorySize, GSM_TOTAL);
    cudaFuncSetAttribute(gemm3_kernel,
                         cudaFuncAttributeMaxDynamicSharedMemorySize, GSM3_TOTAL);

    __nv_bfloat16 *W1h, *W1l, *W2h, *W2l, *W3h, *W3l;
    float *docs, *doc, *u, *G;
    int *rowmap;
    cudaGetSymbolAddress((void**)&W1h, g_W1h);
    cudaGetSymbolAddress((void**)&W1l, g_W1l);
    cudaGetSymbolAddress((void**)&W2h, g_W2h);
    cudaGetSymbolAddress((void**)&W2l, g_W2l);
    cudaGetSymbolAddress((void**)&W3h, g_W3h);
    cudaGetSymbolAddress((void**)&W3l, g_W3l);
    cudaGetSymbolAddress((void**)&docs, g_docs);
    cudaGetSymbolAddress((void**)&doc, g_doc);
    cudaGetSymbolAddress((void**)&u, g_u);
    cudaGetSymbolAddress((void**)&G, g_G);
    cudaGetSymbolAddress((void**)&rowmap, g_rowmap);

    static cudaStream_t s_side = nullptr;
    static cudaEvent_t ev_fork = nullptr, ev_prep = nullptr, ev_join = nullptr;
    if (!s_side) {
        cudaStreamCreateWithFlags(&s_side, cudaStreamNonBlocking);
        cudaEventCreateWithFlags(&ev_fork, cudaEventDisableTiming);
        cudaEventCreateWithFlags(&ev_prep, cudaEventDisableTiming);
        cudaEventCreateWithFlags(&ev_join, cudaEventDisableTiming);
    }

    // legal capture fork: event recorded in the ORIGIN (captured) stream first
    cudaEventRecord(ev_fork, 0);
    cudaStreamWaitEvent(s_side, ev_fork, 0);

    // side stream: prep -> mean -> doc -> u (hidden under main-stream gemm3)
    prep_kernel<<<dim3(256, 3), 256, 0, s_side>>>(fc_w, W_sal, W_nov);
    cudaEventRecord(ev_prep, s_side);
    mean_kernel<<<B, 256, 0, s_side>>>(sent, doc_lens);
    gemm_kernel<<<dim3((B + 127) / 128, 2), 256, GSM_TOTAL, s_side>>>(
        docs, W1h, W1l, doc, B, fc_b, 1);
    gemm_kernel<<<dim3((B + 127) / 128, 2), 256, GSM_TOTAL, s_side>>>(
        doc, W2h, W2l, u, B, w_content, 2);
    cudaEventRecord(ev_join, s_side);

    // main stream: scan -> rowmap -> (wait prep) gemm3 -> (wait join) recur
    scan_kernel<<<1, 256>>>(doc_lens, B, abs_e, rel_e, w_abs, w_rel);
    rowmap_kernel<<<B, 128>>>(doc_lens);
    cudaStreamWaitEvent(0, ev_prep, 0);
    gemm3_kernel<<<(rows_max + 63) / 64, 256, GSM3_TOTAL>>>(
        sent, W3h, W3l, G, rowmap);
    cudaStreamWaitEvent(0, ev_join, 0);
    recur_kernel<<<(B + 7) / 8, 256>>>(sent, bias, doc_lens, B, (float*)d_out);
}